// round 10
// baseline (speedup 1.0000x reference)
#include <cuda_runtime.h>

// Problem constants (fixed by reference: B=32, C=2, H=512, W=512, L=3)
#define BB   32
#define HH   512
#define WW   512
#define LVAL 3.0f
#define ROWS_PER_BLOCK 16
#define NBLOCKS (HH / ROWS_PER_BLOCK * BB)

// Persistent scratch (allocation-free). Zero-initialized at module load;
// the last block resets it after each run so graph replays stay correct.
__device__ double g_part[BB];
__device__ unsigned int g_count = 0;

// Select 5 consecutive floats starting at warp-uniform phase o from two
// aligned float4s (A = block k, B = block k+1).
__device__ __forceinline__ void sel5(const float4 A, const float4 B, const int o, float v[5]) {
    switch (o) {
    case 0:  v[0]=A.x; v[1]=A.y; v[2]=A.z; v[3]=A.w; v[4]=B.x; break;
    case 1:  v[0]=A.y; v[1]=A.z; v[2]=A.w; v[3]=B.x; v[4]=B.y; break;
    case 2:  v[0]=A.z; v[1]=A.w; v[2]=B.x; v[3]=B.y; v[4]=B.z; break;
    default: v[0]=A.w; v[1]=B.x; v[2]=B.y; v[3]=B.z; v[4]=B.w; break;
    }
}

// Grid: (H/16, B). Block: 256 = 2 pair-slots x 128 chunk-threads.
// Thread (s, j) handles pixels x in [4j, 4j+4) of the adjacent row PAIR
// (y, y+1) with y = 16*bx + 2*s + 4*it, it = 0..3. The pair shares the
// middle shifted row r1+1, cutting shifted-window loads 16 -> 12 per pair.
__global__ __launch_bounds__(256, 4) void symloss_kernel(
    const float* __restrict__ Flow,   // (B,2,H,W)
    const float* __restrict__ Asym,   // (B,2)
    const float* __restrict__ Bsym,   // (B,2)
    const float* __restrict__ Mask,   // (B,2,H,W)
    float* __restrict__ out)
{
    const int b  = blockIdx.y;
    const int s  = threadIdx.x >> 7;
    const int j  = threadIdx.x & 127;
    const int x0 = j << 2;
    const int ybase = blockIdx.x * ROWS_PER_BLOCK + 2 * s;

    const float a0 = Asym[2 * b];
    const float a1 = Asym[2 * b + 1];
    const float b0 = Bsym[2 * b];
    const float b1 = Bsym[2 * b + 1];

    const float dxs = -LVAL * a0;
    const float dys = fabsf(LVAL * a1);
    const float dy1 = floorf(dys);
    const float dx1 = floorf(dxs);
    const float fy  = dys - dy1;
    const float fx  = dxs - dx1;
    const int iy1 = (int)dy1;          // >= 0
    const int ix1 = (int)dx1;          // may be negative

    const int hp   = HH - 1 - iy1;
    const int x_lo = max(0, -ix1);
    const int x_hi = min(WW, WW - 1 - ix1);

    const float w11 = (1.f - fx) * (1.f - fy);
    const float w12 = fx * (1.f - fy);
    const float w21 = (1.f - fx) * fy;
    const float w22 = fx * fy;

    // Iteration-invariant chunk geometry.
    const int c0 = x0 + ix1;
    const int o  = c0 & 3;             // warp-uniform (x0 % 4 == 0)
    const int a  = c0 - o;             // 4-aligned
    const bool chunk_live = (x_hi > x_lo) && (x0 + 3 >= x_lo) && (x0 < x_hi);
    const bool fast = chunk_live && (a >= 0) && (a + 8 <= WW);

    float wv[4];                       // 0/1 per-pixel valid weights (iteration-invariant)
    #pragma unroll
    for (int i = 0; i < 4; i++) {
        const int x = x0 + i;
        wv[i] = ((x >= x_lo) && (x < x_hi)) ? 1.f : 0.f;
    }

    const float* f0 = Flow + ((size_t)(2 * b) * HH) * WW;
    const float* f1 = f0 + (size_t)HH * WW;
    const float* m0base = Mask + ((size_t)(2 * b) * HH) * WW;

    float sum = 0.f;

    #pragma unroll 2
    for (int it = 0; it < 4; it++) {
        const int y = ybase + 4 * it;  // top row of the pair
        if (!chunk_live || y >= hp) continue;

        const float rv1 = (y + 1 < hp) ? 1.f : 0.f;  // bottom-row validity
        const int r1 = y + iy1;                      // <= H-2 (y < hp)
        const int r3 = min(r1 + 2, HH - 1);          // clamp: safe when row y+1 invalid

        if (fast) {
            // ---- all 20 loads issued up front ----
            const float* p0r1 = f0 + (size_t)r1 * WW + a;
            const float* p0r2 = p0r1 + WW;
            const float* p0r3 = f0 + (size_t)r3 * WW + a;
            const float* p1r1 = f1 + (size_t)r1 * WW + a;
            const float* p1r2 = p1r1 + WW;
            const float* p1r3 = f1 + (size_t)r3 * WW + a;

            const float4 A00 = *(const float4*)(p0r1);
            const float4 B00 = *(const float4*)(p0r1 + 4);
            const float4 A01 = *(const float4*)(p0r2);
            const float4 B01 = *(const float4*)(p0r2 + 4);
            const float4 A02 = *(const float4*)(p0r3);
            const float4 B02 = *(const float4*)(p0r3 + 4);
            const float4 A10 = *(const float4*)(p1r1);
            const float4 B10 = *(const float4*)(p1r1 + 4);
            const float4 A11 = *(const float4*)(p1r2);
            const float4 B11 = *(const float4*)(p1r2 + 4);
            const float4 A12 = *(const float4*)(p1r3);
            const float4 B12 = *(const float4*)(p1r3 + 4);

            const float* p0y = f0 + (size_t)y * WW + x0;
            const float* p1y = f1 + (size_t)y * WW + x0;
            const float* m0  = m0base + (size_t)y * WW + x0;
            const float* m1  = m0 + (size_t)HH * WW;
            const float4 P0t = *(const float4*)(p0y);
            const float4 P0b = *(const float4*)(p0y + WW);
            const float4 P1t = *(const float4*)(p1y);
            const float4 P1b = *(const float4*)(p1y + WW);
            const float4 M0t = *(const float4*)(m0);
            const float4 M0b = *(const float4*)(m0 + WW);
            const float4 M1t = *(const float4*)(m1);
            const float4 M1b = *(const float4*)(m1 + WW);

            // ---- windows: middle row shared between the two output rows ----
            float v00[5], v01[5], v02[5], v10[5], v11[5], v12[5];
            sel5(A00, B00, o, v00);   // ch0, shifted row r1
            sel5(A01, B01, o, v01);   // ch0, shifted row r1+1 (shared)
            sel5(A02, B02, o, v02);   // ch0, shifted row r1+2
            sel5(A10, B10, o, v10);   // ch1, shifted row r1
            sel5(A11, B11, o, v11);   // ch1, shifted row r1+1 (shared)
            sel5(A12, B12, o, v12);   // ch1, shifted row r1+2

            const float P0ta[4] = {P0t.x, P0t.y, P0t.z, P0t.w};
            const float P0ba[4] = {P0b.x, P0b.y, P0b.z, P0b.w};
            const float P1ta[4] = {P1t.x, P1t.y, P1t.z, P1t.w};
            const float P1ba[4] = {P1b.x, P1b.y, P1b.z, P1b.w};
            const float M0ta[4] = {M0t.x, M0t.y, M0t.z, M0t.w};
            const float M0ba[4] = {M0b.x, M0b.y, M0b.z, M0b.w};
            const float M1ta[4] = {M1t.x, M1t.y, M1t.z, M1t.w};
            const float M1ba[4] = {M1b.x, M1b.y, M1b.z, M1b.w};

            #pragma unroll
            for (int i = 0; i < 4; i++) {
                // row y
                const float pa0 = w11 * v00[i] + w12 * v00[i + 1]
                                + w21 * v01[i] + w22 * v01[i + 1];
                const float pa1 = w11 * v10[i] + w12 * v10[i + 1]
                                + w21 * v11[i] + w22 * v11[i + 1];
                const float da0 = P0ta[i] - pa0;
                const float da1 = P1ta[i] - pa1;
                const float sa  = da1 * b0 - da0 * b1;
                sum += (M0ta[i] + M1ta[i]) * wv[i] * (sa * sa);
                // row y+1 (reuses middle windows v01/v11)
                const float pb0 = w11 * v01[i] + w12 * v01[i + 1]
                                + w21 * v02[i] + w22 * v02[i + 1];
                const float pb1 = w11 * v11[i] + w12 * v11[i + 1]
                                + w21 * v12[i] + w22 * v12[i + 1];
                const float db0 = P0ba[i] - pb0;
                const float db1 = P1ba[i] - pb1;
                const float sb  = db1 * b0 - db0 * b1;
                sum += (M0ba[i] + M1ba[i]) * (wv[i] * rv1) * (sb * sb);
            }
        } else {
            // Edge chunk: scalar loads, only for valid pixels (c in [0, W-2]).
            const float* p0r1 = f0 + (size_t)r1 * WW;
            const float* p0r2 = p0r1 + WW;
            const float* p0r3 = f0 + (size_t)r3 * WW;
            const float* p1r1 = f1 + (size_t)r1 * WW;
            const float* p1r2 = p1r1 + WW;
            const float* p1r3 = f1 + (size_t)r3 * WW;
            const float* p0y  = f0 + (size_t)y * WW;
            const float* p1y  = f1 + (size_t)y * WW;
            const float* m0   = m0base + (size_t)y * WW;
            const float* m1   = m0 + (size_t)HH * WW;
            #pragma unroll
            for (int i = 0; i < 4; i++) {
                if (wv[i] == 0.f) continue;
                const int x = x0 + i;
                const int c = x + ix1;
                // row y
                {
                    const float ph0 = w11 * p0r1[c] + w12 * p0r1[c + 1]
                                    + w21 * p0r2[c] + w22 * p0r2[c + 1];
                    const float ph1 = w11 * p1r1[c] + w12 * p1r1[c + 1]
                                    + w21 * p1r2[c] + w22 * p1r2[c + 1];
                    const float d0 = p0y[x] - ph0;
                    const float d1 = p1y[x] - ph1;
                    const float t  = d1 * b0 - d0 * b1;
                    sum += (m0[x] + m1[x]) * (t * t);
                }
                // row y+1
                if (rv1 != 0.f) {
                    const float ph0 = w11 * p0r2[c] + w12 * p0r2[c + 1]
                                    + w21 * p0r3[c] + w22 * p0r3[c + 1];
                    const float ph1 = w11 * p1r2[c] + w12 * p1r2[c + 1]
                                    + w21 * p1r3[c] + w22 * p1r3[c + 1];
                    const float d0 = p0y[x + WW] - ph0;
                    const float d1 = p1y[x + WW] - ph1;
                    const float t  = d1 * b0 - d0 * b1;
                    sum += (m0[x + WW] + m1[x + WW]) * (t * t);
                }
            }
        }
    }

    // Block reduction: warp shuffle + shared.
    __shared__ float warp_sums[8];
    __shared__ bool  is_last;
    #pragma unroll
    for (int off = 16; off > 0; off >>= 1)
        sum += __shfl_down_sync(0xffffffffu, sum, off);

    const int lane = threadIdx.x & 31;
    const int wid  = threadIdx.x >> 5;
    if (lane == 0) warp_sums[wid] = sum;
    __syncthreads();

    if (threadIdx.x == 0) {
        float total = 0.f;
        #pragma unroll
        for (int wv2 = 0; wv2 < 8; wv2++) total += warp_sums[wv2];
        if (total != 0.f) {
            const float denom = 2.f * (float)max(hp, 1) * (float)max(x_hi - x_lo, 1);
            atomicAdd(&g_part[b], (double)(total / denom) * (1.0 / (double)BB));
        }
        __threadfence();
        const unsigned int prev = atomicAdd(&g_count, 1u);
        is_last = (prev == (unsigned int)(NBLOCKS - 1));
    }
    __syncthreads();

    // Last block finalizes and resets state for the next graph replay.
    if (is_last && threadIdx.x == 0) {
        double acc = 0.0;
        #pragma unroll
        for (int i = 0; i < BB; i++) {
            acc += g_part[i];
            g_part[i] = 0.0;
        }
        out[0] = (float)acc;
        __threadfence();
        g_count = 0;
    }
}

extern "C" void kernel_launch(void* const* d_in, const int* in_sizes, int n_in,
                              void* d_out, int out_size) {
    const float* Flow = (const float*)d_in[0];
    const float* Asym = (const float*)d_in[1];
    const float* Bsym = (const float*)d_in[2];
    const float* Mask = (const float*)d_in[3];
    float* out = (float*)d_out;

    dim3 grid(HH / ROWS_PER_BLOCK, BB);
    symloss_kernel<<<grid, 256>>>(Flow, Asym, Bsym, Mask, out);
}

// round 11
// speedup vs baseline: 1.1078x; 1.1078x over previous
#include <cuda_runtime.h>

// Problem constants (fixed by reference: B=32, C=2, H=512, W=512, L=3)
#define BB   32
#define HH   512
#define WW   512
#define LVAL 3.0f
#define ROWS_PER_BLOCK 16
#define NBLOCKS (HH / ROWS_PER_BLOCK * BB)

// Persistent scratch (allocation-free). Zero-initialized at module load;
// the last block resets it after each run so graph replays stay correct.
__device__ double g_part[BB];
__device__ unsigned int g_count = 0;

// Select 5 consecutive floats starting at warp-uniform phase o from two
// aligned float4s (A = block k, B = block k+1).
__device__ __forceinline__ void sel5(const float4 A, const float4 B, const int o, float v[5]) {
    switch (o) {
    case 0:  v[0]=A.x; v[1]=A.y; v[2]=A.z; v[3]=A.w; v[4]=B.x; break;
    case 1:  v[0]=A.y; v[1]=A.z; v[2]=A.w; v[3]=B.x; v[4]=B.y; break;
    case 2:  v[0]=A.z; v[1]=A.w; v[2]=B.x; v[3]=B.y; v[4]=B.z; break;
    default: v[0]=A.w; v[1]=B.x; v[2]=B.y; v[3]=B.z; v[4]=B.w; break;
    }
}

// Grid: (H/16, B). Block: 256 = 2 subrows x 128 chunk-threads.
// Thread (s, j) handles pixels x in [4j, 4j+4) of rows y = 16*bx + s + 2*it, it=0..7.
// launch_bounds (256, 3): give ptxas register headroom (~84) so the unroll-2
// iteration pair can front-batch its 24 float4 loads for ~2x per-warp MLP.
__global__ __launch_bounds__(256, 3) void symloss_kernel(
    const float* __restrict__ Flow,   // (B,2,H,W)
    const float* __restrict__ Asym,   // (B,2)
    const float* __restrict__ Bsym,   // (B,2)
    const float* __restrict__ Mask,   // (B,2,H,W)
    float* __restrict__ out)
{
    const int b  = blockIdx.y;
    const int s  = threadIdx.x >> 7;
    const int j  = threadIdx.x & 127;
    const int x0 = j << 2;
    const int ybase = blockIdx.x * ROWS_PER_BLOCK + s;

    const float a0 = Asym[2 * b];
    const float a1 = Asym[2 * b + 1];
    const float b0 = Bsym[2 * b];
    const float b1 = Bsym[2 * b + 1];

    const float dxs = -LVAL * a0;
    const float dys = fabsf(LVAL * a1);
    const float dy1 = floorf(dys);
    const float dx1 = floorf(dxs);
    const float fy  = dys - dy1;
    const float fx  = dxs - dx1;
    const int iy1 = (int)dy1;          // >= 0
    const int ix1 = (int)dx1;          // may be negative

    const int hp   = HH - 1 - iy1;
    const int x_lo = max(0, -ix1);
    const int x_hi = min(WW, WW - 1 - ix1);

    const float w11 = (1.f - fx) * (1.f - fy);
    const float w12 = fx * (1.f - fy);
    const float w21 = (1.f - fx) * fy;
    const float w22 = fx * fy;

    // Iteration-invariant chunk geometry.
    const int c0 = x0 + ix1;
    const int o  = c0 & 3;             // warp-uniform (x0 % 4 == 0)
    const int a  = c0 - o;             // 4-aligned
    const bool chunk_live = (x_hi > x_lo) && (x0 + 3 >= x_lo) && (x0 < x_hi);
    const bool fast = chunk_live && (a >= 0) && (a + 8 <= WW);

    float wv[4];                       // 0/1 per-pixel valid weights (iteration-invariant)
    #pragma unroll
    for (int i = 0; i < 4; i++) {
        const int x = x0 + i;
        wv[i] = ((x >= x_lo) && (x < x_hi)) ? 1.f : 0.f;
    }

    const float* f0 = Flow + ((size_t)(2 * b) * HH) * WW;
    const float* f1 = f0 + (size_t)HH * WW;
    const float* m0base = Mask + ((size_t)(2 * b) * HH) * WW;

    float sum = 0.f;

    #pragma unroll 2
    for (int it = 0; it < ROWS_PER_BLOCK / 2; it++) {
        const int y = ybase + 2 * it;
        if (!chunk_live || y >= hp) continue;

        const int r1 = y + iy1;        // <= H-2 for valid rows
        const float* m0 = m0base + (size_t)y * WW;
        const float* m1 = m0 + (size_t)HH * WW;

        const float4 M0 = *(const float4*)(m0 + x0);
        const float4 M1 = *(const float4*)(m1 + x0);
        const float4 P0 = *(const float4*)(f0 + (size_t)y * WW + x0);
        const float4 P1 = *(const float4*)(f1 + (size_t)y * WW + x0);
        const float M0a[4] = {M0.x, M0.y, M0.z, M0.w};
        const float M1a[4] = {M1.x, M1.y, M1.z, M1.w};
        const float P0a[4] = {P0.x, P0.y, P0.z, P0.w};
        const float P1a[4] = {P1.x, P1.y, P1.z, P1.w};

        if (fast) {
            const float* p0r1 = f0 + (size_t)r1 * WW + a;
            const float* p0r2 = p0r1 + WW;
            const float* p1r1 = f1 + (size_t)r1 * WW + a;
            const float* p1r2 = p1r1 + WW;
            const float4 A00 = *(const float4*)(p0r1);
            const float4 B00 = *(const float4*)(p0r1 + 4);
            const float4 A01 = *(const float4*)(p0r2);
            const float4 B01 = *(const float4*)(p0r2 + 4);
            const float4 A10 = *(const float4*)(p1r1);
            const float4 B10 = *(const float4*)(p1r1 + 4);
            const float4 A11 = *(const float4*)(p1r2);
            const float4 B11 = *(const float4*)(p1r2 + 4);

            float v00[5], v01[5], v10[5], v11[5];
            sel5(A00, B00, o, v00);   // ch0, row r1: flow0[r1][c0 .. c0+4]
            sel5(A01, B01, o, v01);   // ch0, row r2
            sel5(A10, B10, o, v10);   // ch1, row r1
            sel5(A11, B11, o, v11);   // ch1, row r2

            #pragma unroll
            for (int i = 0; i < 4; i++) {
                const float ph0 = w11 * v00[i] + w12 * v00[i + 1]
                                + w21 * v01[i] + w22 * v01[i + 1];
                const float ph1 = w11 * v10[i] + w12 * v10[i + 1]
                                + w21 * v11[i] + w22 * v11[i + 1];
                const float d0 = P0a[i] - ph0;
                const float d1 = P1a[i] - ph1;
                const float sq = d1 * b0 - d0 * b1;
                sum += (M0a[i] + M1a[i]) * wv[i] * (sq * sq);
            }
        } else {
            // Edge chunk: scalar loads, only for valid pixels (c in [0, W-2]).
            const float* p0r1 = f0 + (size_t)r1 * WW;
            const float* p0r2 = p0r1 + WW;
            const float* p1r1 = f1 + (size_t)r1 * WW;
            const float* p1r2 = p1r1 + WW;
            #pragma unroll
            for (int i = 0; i < 4; i++) {
                if (wv[i] == 0.f) continue;
                const int c = x0 + i + ix1;
                const float ph0 = w11 * p0r1[c] + w12 * p0r1[c + 1]
                                + w21 * p0r2[c] + w22 * p0r2[c + 1];
                const float ph1 = w11 * p1r1[c] + w12 * p1r1[c + 1]
                                + w21 * p1r2[c] + w22 * p1r2[c + 1];
                const float d0 = P0a[i] - ph0;
                const float d1 = P1a[i] - ph1;
                const float sq = d1 * b0 - d0 * b1;
                sum += (M0a[i] + M1a[i]) * (sq * sq);
            }
        }
    }

    // Block reduction: warp shuffle + shared.
    __shared__ float warp_sums[8];
    __shared__ bool  is_last;
    #pragma unroll
    for (int off = 16; off > 0; off >>= 1)
        sum += __shfl_down_sync(0xffffffffu, sum, off);

    const int lane = threadIdx.x & 31;
    const int wid  = threadIdx.x >> 5;
    if (lane == 0) warp_sums[wid] = sum;
    __syncthreads();

    if (threadIdx.x == 0) {
        float total = 0.f;
        #pragma unroll
        for (int wv2 = 0; wv2 < 8; wv2++) total += warp_sums[wv2];
        if (total != 0.f) {
            const float denom = 2.f * (float)max(hp, 1) * (float)max(x_hi - x_lo, 1);
            atomicAdd(&g_part[b], (double)(total / denom) * (1.0 / (double)BB));
        }
        __threadfence();
        const unsigned int prev = atomicAdd(&g_count, 1u);
        is_last = (prev == (unsigned int)(NBLOCKS - 1));
    }
    __syncthreads();

    // Last block finalizes and resets state for the next graph replay.
    if (is_last && threadIdx.x == 0) {
        double acc = 0.0;
        #pragma unroll
        for (int i = 0; i < BB; i++) {
            acc += g_part[i];
            g_part[i] = 0.0;
        }
        out[0] = (float)acc;
        __threadfence();
        g_count = 0;
    }
}

extern "C" void kernel_launch(void* const* d_in, const int* in_sizes, int n_in,
                              void* d_out, int out_size) {
    const float* Flow = (const float*)d_in[0];
    const float* Asym = (const float*)d_in[1];
    const float* Bsym = (const float*)d_in[2];
    const float* Mask = (const float*)d_in[3];
    float* out = (float*)d_out;

    dim3 grid(HH / ROWS_PER_BLOCK, BB);
    symloss_kernel<<<grid, 256>>>(Flow, Asym, Bsym, Mask, out);
}

// round 12
// speedup vs baseline: 1.3737x; 1.2400x over previous
#include <cuda_runtime.h>

// Problem constants (fixed by reference: B=32, C=2, H=512, W=512, L=3)
#define BB   32
#define HH   512
#define WW   512
#define LVAL 3.0f
#define ROWS_PER_BLOCK 16
#define NBLOCKS (HH / ROWS_PER_BLOCK * BB)

// Persistent scratch (allocation-free). Zero-initialized at module load;
// the last block resets it after each run so graph replays stay correct.
__device__ double g_part[BB];
__device__ unsigned int g_count = 0;

// Select 5 consecutive floats starting at warp-uniform phase o from two
// aligned float4s (A = block k, B = block k+1).
__device__ __forceinline__ void sel5(const float4 A, const float4 B, const int o, float v[5]) {
    switch (o) {
    case 0:  v[0]=A.x; v[1]=A.y; v[2]=A.z; v[3]=A.w; v[4]=B.x; break;
    case 1:  v[0]=A.y; v[1]=A.z; v[2]=A.w; v[3]=B.x; v[4]=B.y; break;
    case 2:  v[0]=A.z; v[1]=A.w; v[2]=B.x; v[3]=B.y; v[4]=B.z; break;
    default: v[0]=A.w; v[1]=B.x; v[2]=B.y; v[3]=B.z; v[4]=B.w; break;
    }
}

// Grid: (H/16, B). Block: 256 = 2 subrows x 128 chunk-threads.
// Thread (s, j) handles pixels x in [4j, 4j+4) of rows y = 16*bx + s + 2*it, it=0..7.
// Mask is pure-streaming (each byte read once) -> __ldcs evict-first, so the
// reused Flow tensor (64MB ~ half of L2) stays L2-resident within and across
// graph replays. Flow loads keep the default caching policy.
__global__ __launch_bounds__(256, 4) void symloss_kernel(
    const float* __restrict__ Flow,   // (B,2,H,W)
    const float* __restrict__ Asym,   // (B,2)
    const float* __restrict__ Bsym,   // (B,2)
    const float* __restrict__ Mask,   // (B,2,H,W)
    float* __restrict__ out)
{
    const int b  = blockIdx.y;
    const int s  = threadIdx.x >> 7;
    const int j  = threadIdx.x & 127;
    const int x0 = j << 2;
    const int ybase = blockIdx.x * ROWS_PER_BLOCK + s;

    const float a0 = Asym[2 * b];
    const float a1 = Asym[2 * b + 1];
    const float b0 = Bsym[2 * b];
    const float b1 = Bsym[2 * b + 1];

    const float dxs = -LVAL * a0;
    const float dys = fabsf(LVAL * a1);
    const float dy1 = floorf(dys);
    const float dx1 = floorf(dxs);
    const float fy  = dys - dy1;
    const float fx  = dxs - dx1;
    const int iy1 = (int)dy1;          // >= 0
    const int ix1 = (int)dx1;          // may be negative

    const int hp   = HH - 1 - iy1;
    const int x_lo = max(0, -ix1);
    const int x_hi = min(WW, WW - 1 - ix1);

    const float w11 = (1.f - fx) * (1.f - fy);
    const float w12 = fx * (1.f - fy);
    const float w21 = (1.f - fx) * fy;
    const float w22 = fx * fy;

    // Iteration-invariant chunk geometry.
    const int c0 = x0 + ix1;
    const int o  = c0 & 3;             // warp-uniform (x0 % 4 == 0)
    const int a  = c0 - o;             // 4-aligned
    const bool chunk_live = (x_hi > x_lo) && (x0 + 3 >= x_lo) && (x0 < x_hi);
    const bool fast = chunk_live && (a >= 0) && (a + 8 <= WW);

    float wv[4];                       // 0/1 per-pixel valid weights (iteration-invariant)
    #pragma unroll
    for (int i = 0; i < 4; i++) {
        const int x = x0 + i;
        wv[i] = ((x >= x_lo) && (x < x_hi)) ? 1.f : 0.f;
    }

    const float* f0 = Flow + ((size_t)(2 * b) * HH) * WW;
    const float* f1 = f0 + (size_t)HH * WW;
    const float* m0base = Mask + ((size_t)(2 * b) * HH) * WW;

    float sum = 0.f;

    #pragma unroll 2
    for (int it = 0; it < ROWS_PER_BLOCK / 2; it++) {
        const int y = ybase + 2 * it;
        if (!chunk_live || y >= hp) continue;

        const int r1 = y + iy1;        // <= H-2 for valid rows
        const float* m0 = m0base + (size_t)y * WW;
        const float* m1 = m0 + (size_t)HH * WW;

        const float4 M0 = __ldcs((const float4*)(m0 + x0));   // streaming, evict-first
        const float4 M1 = __ldcs((const float4*)(m1 + x0));   // streaming, evict-first
        const float4 P0 = *(const float4*)(f0 + (size_t)y * WW + x0);
        const float4 P1 = *(const float4*)(f1 + (size_t)y * WW + x0);
        const float M0a[4] = {M0.x, M0.y, M0.z, M0.w};
        const float M1a[4] = {M1.x, M1.y, M1.z, M1.w};
        const float P0a[4] = {P0.x, P0.y, P0.z, P0.w};
        const float P1a[4] = {P1.x, P1.y, P1.z, P1.w};

        if (fast) {
            const float* p0r1 = f0 + (size_t)r1 * WW + a;
            const float* p0r2 = p0r1 + WW;
            const float* p1r1 = f1 + (size_t)r1 * WW + a;
            const float* p1r2 = p1r1 + WW;
            const float4 A00 = *(const float4*)(p0r1);
            const float4 B00 = *(const float4*)(p0r1 + 4);
            const float4 A01 = *(const float4*)(p0r2);
            const float4 B01 = *(const float4*)(p0r2 + 4);
            const float4 A10 = *(const float4*)(p1r1);
            const float4 B10 = *(const float4*)(p1r1 + 4);
            const float4 A11 = *(const float4*)(p1r2);
            const float4 B11 = *(const float4*)(p1r2 + 4);

            float v00[5], v01[5], v10[5], v11[5];
            sel5(A00, B00, o, v00);   // ch0, row r1: flow0[r1][c0 .. c0+4]
            sel5(A01, B01, o, v01);   // ch0, row r2
            sel5(A10, B10, o, v10);   // ch1, row r1
            sel5(A11, B11, o, v11);   // ch1, row r2

            #pragma unroll
            for (int i = 0; i < 4; i++) {
                const float ph0 = w11 * v00[i] + w12 * v00[i + 1]
                                + w21 * v01[i] + w22 * v01[i + 1];
                const float ph1 = w11 * v10[i] + w12 * v10[i + 1]
                                + w21 * v11[i] + w22 * v11[i + 1];
                const float d0 = P0a[i] - ph0;
                const float d1 = P1a[i] - ph1;
                const float sq = d1 * b0 - d0 * b1;
                sum += (M0a[i] + M1a[i]) * wv[i] * (sq * sq);
            }
        } else {
            // Edge chunk: scalar loads, only for valid pixels (c in [0, W-2]).
            const float* p0r1 = f0 + (size_t)r1 * WW;
            const float* p0r2 = p0r1 + WW;
            const float* p1r1 = f1 + (size_t)r1 * WW;
            const float* p1r2 = p1r1 + WW;
            #pragma unroll
            for (int i = 0; i < 4; i++) {
                if (wv[i] == 0.f) continue;
                const int c = x0 + i + ix1;
                const float ph0 = w11 * p0r1[c] + w12 * p0r1[c + 1]
                                + w21 * p0r2[c] + w22 * p0r2[c + 1];
                const float ph1 = w11 * p1r1[c] + w12 * p1r1[c + 1]
                                + w21 * p1r2[c] + w22 * p1r2[c + 1];
                const float d0 = P0a[i] - ph0;
                const float d1 = P1a[i] - ph1;
                const float sq = d1 * b0 - d0 * b1;
                sum += (M0a[i] + M1a[i]) * (sq * sq);
            }
        }
    }

    // Block reduction: warp shuffle + shared.
    __shared__ float warp_sums[8];
    __shared__ bool  is_last;
    #pragma unroll
    for (int off = 16; off > 0; off >>= 1)
        sum += __shfl_down_sync(0xffffffffu, sum, off);

    const int lane = threadIdx.x & 31;
    const int wid  = threadIdx.x >> 5;
    if (lane == 0) warp_sums[wid] = sum;
    __syncthreads();

    if (threadIdx.x == 0) {
        float total = 0.f;
        #pragma unroll
        for (int wv2 = 0; wv2 < 8; wv2++) total += warp_sums[wv2];
        if (total != 0.f) {
            const float denom = 2.f * (float)max(hp, 1) * (float)max(x_hi - x_lo, 1);
            atomicAdd(&g_part[b], (double)(total / denom) * (1.0 / (double)BB));
        }
        __threadfence();
        const unsigned int prev = atomicAdd(&g_count, 1u);
        is_last = (prev == (unsigned int)(NBLOCKS - 1));
    }
    __syncthreads();

    // Last block finalizes and resets state for the next graph replay.
    if (is_last && threadIdx.x == 0) {
        double acc = 0.0;
        #pragma unroll
        for (int i = 0; i < BB; i++) {
            acc += g_part[i];
            g_part[i] = 0.0;
        }
        out[0] = (float)acc;
        __threadfence();
        g_count = 0;
    }
}

extern "C" void kernel_launch(void* const* d_in, const int* in_sizes, int n_in,
                              void* d_out, int out_size) {
    const float* Flow = (const float*)d_in[0];
    const float* Asym = (const float*)d_in[1];
    const float* Bsym = (const float*)d_in[2];
    const float* Mask = (const float*)d_in[3];
    float* out = (float*)d_out;

    dim3 grid(HH / ROWS_PER_BLOCK, BB);
    symloss_kernel<<<grid, 256>>>(Flow, Asym, Bsym, Mask, out);
}

// round 13
// speedup vs baseline: 1.5255x; 1.1105x over previous
#include <cuda_runtime.h>

// Problem constants (fixed by reference: B=32, C=2, H=512, W=512, L=3)
#define BB   32
#define HH   512
#define WW   512
#define LVAL 3.0f
#define ROWS_PER_BLOCK 16
#define NBLOCKS (HH / ROWS_PER_BLOCK * BB)

// Persistent scratch (allocation-free). Zero-initialized at module load;
// the last block resets it after each run so graph replays stay correct.
__device__ double g_part[BB];
__device__ unsigned int g_count = 0;

// Compile-time select of 5 consecutive floats at phase O from two aligned
// float4s. Pure register renaming — zero instructions at runtime.
template <int O>
__device__ __forceinline__ void sel5_t(const float4 A, const float4 B, float v[5]) {
    if constexpr (O == 0) { v[0]=A.x; v[1]=A.y; v[2]=A.z; v[3]=A.w; v[4]=B.x; }
    else if constexpr (O == 1) { v[0]=A.y; v[1]=A.z; v[2]=A.w; v[3]=B.x; v[4]=B.y; }
    else if constexpr (O == 2) { v[0]=A.z; v[1]=A.w; v[2]=B.x; v[3]=B.y; v[4]=B.z; }
    else { v[0]=A.w; v[1]=B.x; v[2]=B.y; v[3]=B.z; v[4]=B.w; }
}

// Row loop specialized on the (block-uniform) window phase O.
template <int O>
__device__ __forceinline__ float run_rows(
    const float* __restrict__ f0, const float* __restrict__ f1,
    const float* __restrict__ m0base,
    int ybase, int hp, int iy1, int ix1, int a, int x0,
    bool chunk_live, bool fast,
    float w11, float w12, float w21, float w22,
    float b0, float b1, const float wv[4])
{
    float sum = 0.f;

    #pragma unroll 2
    for (int it = 0; it < ROWS_PER_BLOCK / 2; it++) {
        const int y = ybase + 2 * it;
        if (!chunk_live || y >= hp) continue;

        const int r1 = y + iy1;        // <= H-2 for valid rows
        const float* m0 = m0base + (size_t)y * WW;
        const float* m1 = m0 + (size_t)HH * WW;

        const float4 M0 = __ldcs((const float4*)(m0 + x0));   // streaming, evict-first
        const float4 M1 = __ldcs((const float4*)(m1 + x0));   // streaming, evict-first
        const float4 P0 = *(const float4*)(f0 + (size_t)y * WW + x0);
        const float4 P1 = *(const float4*)(f1 + (size_t)y * WW + x0);
        const float M0a[4] = {M0.x, M0.y, M0.z, M0.w};
        const float M1a[4] = {M1.x, M1.y, M1.z, M1.w};
        const float P0a[4] = {P0.x, P0.y, P0.z, P0.w};
        const float P1a[4] = {P1.x, P1.y, P1.z, P1.w};

        if (fast) {
            const float* p0r1 = f0 + (size_t)r1 * WW + a;
            const float* p0r2 = p0r1 + WW;
            const float* p1r1 = f1 + (size_t)r1 * WW + a;
            const float* p1r2 = p1r1 + WW;
            const float4 A00 = *(const float4*)(p0r1);
            const float4 B00 = *(const float4*)(p0r1 + 4);
            const float4 A01 = *(const float4*)(p0r2);
            const float4 B01 = *(const float4*)(p0r2 + 4);
            const float4 A10 = *(const float4*)(p1r1);
            const float4 B10 = *(const float4*)(p1r1 + 4);
            const float4 A11 = *(const float4*)(p1r2);
            const float4 B11 = *(const float4*)(p1r2 + 4);

            float v00[5], v01[5], v10[5], v11[5];
            sel5_t<O>(A00, B00, v00);   // ch0, row r1: flow0[r1][c0 .. c0+4]
            sel5_t<O>(A01, B01, v01);   // ch0, row r2
            sel5_t<O>(A10, B10, v10);   // ch1, row r1
            sel5_t<O>(A11, B11, v11);   // ch1, row r2

            #pragma unroll
            for (int i = 0; i < 4; i++) {
                const float ph0 = w11 * v00[i] + w12 * v00[i + 1]
                                + w21 * v01[i] + w22 * v01[i + 1];
                const float ph1 = w11 * v10[i] + w12 * v10[i + 1]
                                + w21 * v11[i] + w22 * v11[i + 1];
                const float d0 = P0a[i] - ph0;
                const float d1 = P1a[i] - ph1;
                const float sq = d1 * b0 - d0 * b1;
                sum += (M0a[i] + M1a[i]) * wv[i] * (sq * sq);
            }
        } else {
            // Edge chunk: scalar loads, only for valid pixels (c in [0, W-2]).
            const float* p0r1 = f0 + (size_t)r1 * WW;
            const float* p0r2 = p0r1 + WW;
            const float* p1r1 = f1 + (size_t)r1 * WW;
            const float* p1r2 = p1r1 + WW;
            #pragma unroll
            for (int i = 0; i < 4; i++) {
                if (wv[i] == 0.f) continue;
                const int c = x0 + i + ix1;
                const float ph0 = w11 * p0r1[c] + w12 * p0r1[c + 1]
                                + w21 * p0r2[c] + w22 * p0r2[c + 1];
                const float ph1 = w11 * p1r1[c] + w12 * p1r1[c + 1]
                                + w21 * p1r2[c] + w22 * p1r2[c + 1];
                const float d0 = P0a[i] - ph0;
                const float d1 = P1a[i] - ph1;
                const float sq = d1 * b0 - d0 * b1;
                sum += (M0a[i] + M1a[i]) * (sq * sq);
            }
        }
    }
    return sum;
}

// Grid: (H/16, B). Block: 256 = 2 subrows x 128 chunk-threads.
// Thread (s, j) handles pixels x in [4j, 4j+4) of rows y = 16*bx + s + 2*it, it=0..7.
__global__ __launch_bounds__(256, 4) void symloss_kernel(
    const float* __restrict__ Flow,   // (B,2,H,W)
    const float* __restrict__ Asym,   // (B,2)
    const float* __restrict__ Bsym,   // (B,2)
    const float* __restrict__ Mask,   // (B,2,H,W)
    float* __restrict__ out)
{
    const int b  = blockIdx.y;
    const int s  = threadIdx.x >> 7;
    const int j  = threadIdx.x & 127;
    const int x0 = j << 2;
    const int ybase = blockIdx.x * ROWS_PER_BLOCK + s;

    const float a0 = Asym[2 * b];
    const float a1 = Asym[2 * b + 1];
    const float b0 = Bsym[2 * b];
    const float b1 = Bsym[2 * b + 1];

    const float dxs = -LVAL * a0;
    const float dys = fabsf(LVAL * a1);
    const float dy1 = floorf(dys);
    const float dx1 = floorf(dxs);
    const float fy  = dys - dy1;
    const float fx  = dxs - dx1;
    const int iy1 = (int)dy1;          // >= 0
    const int ix1 = (int)dx1;          // may be negative

    const int hp   = HH - 1 - iy1;
    const int x_lo = max(0, -ix1);
    const int x_hi = min(WW, WW - 1 - ix1);

    const float w11 = (1.f - fx) * (1.f - fy);
    const float w12 = fx * (1.f - fy);
    const float w21 = (1.f - fx) * fy;
    const float w22 = fx * fy;

    // Iteration-invariant chunk geometry.
    const int c0 = x0 + ix1;
    const int o  = c0 & 3;             // block-uniform (x0 % 4 == 0, ix1 sample-constant)
    const int a  = c0 - o;             // 4-aligned
    const bool chunk_live = (x_hi > x_lo) && (x0 + 3 >= x_lo) && (x0 < x_hi);
    const bool fast = chunk_live && (a >= 0) && (a + 8 <= WW);

    float wv[4];                       // 0/1 per-pixel valid weights (iteration-invariant)
    #pragma unroll
    for (int i = 0; i < 4; i++) {
        const int x = x0 + i;
        wv[i] = ((x >= x_lo) && (x < x_hi)) ? 1.f : 0.f;
    }

    const float* f0 = Flow + ((size_t)(2 * b) * HH) * WW;
    const float* f1 = f0 + (size_t)HH * WW;
    const float* m0base = Mask + ((size_t)(2 * b) * HH) * WW;

    // One uniform dispatch on the block-constant phase; sel5 becomes free.
    float sum;
    switch (o) {
    case 0:  sum = run_rows<0>(f0, f1, m0base, ybase, hp, iy1, ix1, a, x0,
                               chunk_live, fast, w11, w12, w21, w22, b0, b1, wv); break;
    case 1:  sum = run_rows<1>(f0, f1, m0base, ybase, hp, iy1, ix1, a, x0,
                               chunk_live, fast, w11, w12, w21, w22, b0, b1, wv); break;
    case 2:  sum = run_rows<2>(f0, f1, m0base, ybase, hp, iy1, ix1, a, x0,
                               chunk_live, fast, w11, w12, w21, w22, b0, b1, wv); break;
    default: sum = run_rows<3>(f0, f1, m0base, ybase, hp, iy1, ix1, a, x0,
                               chunk_live, fast, w11, w12, w21, w22, b0, b1, wv); break;
    }

    // Block reduction: warp shuffle + shared.
    __shared__ float warp_sums[8];
    __shared__ bool  is_last;
    #pragma unroll
    for (int off = 16; off > 0; off >>= 1)
        sum += __shfl_down_sync(0xffffffffu, sum, off);

    const int lane = threadIdx.x & 31;
    const int wid  = threadIdx.x >> 5;
    if (lane == 0) warp_sums[wid] = sum;
    __syncthreads();

    if (threadIdx.x == 0) {
        float total = 0.f;
        #pragma unroll
        for (int wv2 = 0; wv2 < 8; wv2++) total += warp_sums[wv2];
        if (total != 0.f) {
            const float denom = 2.f * (float)max(hp, 1) * (float)max(x_hi - x_lo, 1);
            atomicAdd(&g_part[b], (double)(total / denom) * (1.0 / (double)BB));
        }
        __threadfence();
        const unsigned int prev = atomicAdd(&g_count, 1u);
        is_last = (prev == (unsigned int)(NBLOCKS - 1));
    }
    __syncthreads();

    // Last block finalizes and resets state for the next graph replay.
    if (is_last && threadIdx.x == 0) {
        double acc = 0.0;
        #pragma unroll
        for (int i = 0; i < BB; i++) {
            acc += g_part[i];
            g_part[i] = 0.0;
        }
        out[0] = (float)acc;
        __threadfence();
        g_count = 0;
    }
}

extern "C" void kernel_launch(void* const* d_in, const int* in_sizes, int n_in,
                              void* d_out, int out_size) {
    const float* Flow = (const float*)d_in[0];
    const float* Asym = (const float*)d_in[1];
    const float* Bsym = (const float*)d_in[2];
    const float* Mask = (const float*)d_in[3];
    float* out = (float*)d_out;

    dim3 grid(HH / ROWS_PER_BLOCK, BB);
    symloss_kernel<<<grid, 256>>>(Flow, Asym, Bsym, Mask, out);
}